// round 1
// baseline (speedup 1.0000x reference)
#include <cuda_runtime.h>

#define BB 16
#define HH 1024
#define WW 1024
#define R 4
#define KS 9
#define TX 64
#define TY 32
#define NT 256
#define IW (TX + 2*R)   // 72
#define IH (TY + 2*R)   // 40
#define ROWS_PER_THREAD (TY / (NT / TX))   // 8

__device__ double g_loss_acc;

__global__ void zero_acc_kernel() { g_loss_acc = 0.0; }

__global__ void finalize_kernel(float* out) {
    out[0] = (float)(g_loss_acc / (double)((long long)BB * HH * WW));
}

__global__ __launch_bounds__(NT) void snake_fused_kernel(
    const float* __restrict__ pred,
    const float* __restrict__ snake,
    const float* __restrict__ fltr,
    float* __restrict__ out)
{
    __shared__ float s_in[IH][IW];       // 40 x 72 input tile (with halo)
    __shared__ float s_hg[IH][TX];       // horizontal conv with g
    __shared__ float s_hd[IH][TX];       // horizontal conv with dg
    __shared__ float s_g[KS], s_dg[KS];
    __shared__ float s_red[NT / 32];

    const int tid = threadIdx.x;
    const int bx = blockIdx.x;   // W / TX = 16
    const int by = blockIdx.y;   // H / TY = 32
    const int b  = blockIdx.z;   // B = 16

    // --- recover separable taps from fltr (f_dy = outer(dg, g), sum(g)=1) ---
    if (tid < KS) {
        float s = 0.f;
        #pragma unroll
        for (int j = 0; j < KS; ++j) s += fltr[tid * KS + j];  // row-sum of f_dy -> dg[i]
        s_dg[tid] = s;
    }
    __syncthreads();
    if (tid < KS) {
        s_g[tid] = fltr[tid] / s_dg[0];  // f_dy[0][j] / dg[0] = g[j]
    }

    // --- load input tile with halo (zero-padded SAME) ---
    const int x0 = bx * TX - R;
    const int y0 = by * TY - R;
    const size_t plane = (size_t)HH * WW;
    const float* pb = pred + (size_t)b * plane;
    for (int i = tid; i < IW * IH; i += NT) {
        int rx = i % IW, ry = i / IW;
        int gx = x0 + rx, gy = y0 + ry;
        float v = 0.f;
        if (gx >= 0 && gx < WW && gy >= 0 && gy < HH) v = pb[(size_t)gy * WW + gx];
        s_in[ry][rx] = v;
    }
    __syncthreads();

    float rg[KS], rdg[KS];
    #pragma unroll
    for (int j = 0; j < KS; ++j) { rg[j] = s_g[j]; rdg[j] = s_dg[j]; }

    const int tx  = tid % TX;
    const int tyb = tid / TX;   // 0..3
    float* out_gimg  = out + 1;
    float* out_gimgW = out + 1 + (size_t)BB * 2 * plane;
    const float* sb = snake + (size_t)b * plane;

    // ================= Phase A: raw conv + loss =================
    for (int i = tid; i < IH * TX; i += NT) {
        int cx = i % TX, ry = i / TX;
        float sg = 0.f, sd = 0.f;
        #pragma unroll
        for (int j = 0; j < KS; ++j) {
            float v = s_in[ry][cx + j];
            sg = fmaf(rg[j],  v, sg);
            sd = fmaf(rdg[j], v, sd);
        }
        s_hg[ry][cx] = sg;
        s_hd[ry][cx] = sd;
    }
    __syncthreads();

    float lacc = 0.f;
    #pragma unroll
    for (int k = 0; k < ROWS_PER_THREAD; ++k) {
        int ty = tyb + k * (NT / TX);
        float ady = 0.f, adx = 0.f;
        #pragma unroll
        for (int j = 0; j < KS; ++j) {
            ady = fmaf(rdg[j], s_hg[ty + j][tx], ady);  // dy channel: dg over y, g over x
            adx = fmaf(rg[j],  s_hd[ty + j][tx], adx);  // dx channel: g over y, dg over x
        }
        int gy = by * TY + ty;
        int gx = bx * TX + tx;
        size_t pix = (size_t)gy * WW + gx;
        out_gimg[((size_t)b * 2 + 0) * plane + pix] = 10.0f * ady;
        out_gimg[((size_t)b * 2 + 1) * plane + pix] = 10.0f * adx;

        // loss: sd = s>0 ? DMAX : 2*s ; weight = 1 + 1.5*(s<0)
        float p = s_in[ty + R][tx + R];
        float s = sb[pix];
        float sdv = (s > 0.f) ? 15.0f : 2.0f * s;
        float w   = (s < 0.f) ? 2.5f : 1.0f;
        float d = p - sdv;
        lacc = fmaf(d * d, w, lacc);
    }
    __syncthreads();   // done reading s_hg/s_hd/s_in(loss) before overwrite

    // ================= Phase B: abs(pred) conv =================
    for (int i = tid; i < IH * TX; i += NT) {
        int cx = i % TX, ry = i / TX;
        float sg = 0.f, sd = 0.f;
        #pragma unroll
        for (int j = 0; j < KS; ++j) {
            float v = fabsf(s_in[ry][cx + j]);
            sg = fmaf(rg[j],  v, sg);
            sd = fmaf(rdg[j], v, sd);
        }
        s_hg[ry][cx] = sg;
        s_hd[ry][cx] = sd;
    }
    __syncthreads();

    #pragma unroll
    for (int k = 0; k < ROWS_PER_THREAD; ++k) {
        int ty = tyb + k * (NT / TX);
        float ady = 0.f, adx = 0.f;
        #pragma unroll
        for (int j = 0; j < KS; ++j) {
            ady = fmaf(rdg[j], s_hg[ty + j][tx], ady);
            adx = fmaf(rg[j],  s_hd[ty + j][tx], adx);
        }
        int gy = by * TY + ty;
        int gx = bx * TX + tx;
        size_t pix = (size_t)gy * WW + gx;
        out_gimgW[((size_t)b * 2 + 0) * plane + pix] = 10.0f * ady;
        out_gimgW[((size_t)b * 2 + 1) * plane + pix] = 10.0f * adx;
    }

    // ================= loss block reduce =================
    #pragma unroll
    for (int off = 16; off; off >>= 1)
        lacc += __shfl_down_sync(0xffffffffu, lacc, off);
    if ((tid & 31) == 0) s_red[tid >> 5] = lacc;
    __syncthreads();
    if (tid < NT / 32) {
        float v = s_red[tid];
        #pragma unroll
        for (int off = (NT / 64); off; off >>= 1)
            v += __shfl_down_sync(0xffu, v, off);
        if (tid == 0) atomicAdd(&g_loss_acc, (double)v);
    }
}

extern "C" void kernel_launch(void* const* d_in, const int* in_sizes, int n_in,
                              void* d_out, int out_size) {
    const float* pred  = (const float*)d_in[0];
    const float* snake = (const float*)d_in[1];
    const float* fltr  = (const float*)d_in[2];
    float* out = (float*)d_out;

    zero_acc_kernel<<<1, 1>>>();
    dim3 grid(WW / TX, HH / TY, BB);
    snake_fused_kernel<<<grid, NT>>>(pred, snake, fltr, out);
    finalize_kernel<<<1, 1>>>(out);
}

// round 2
// speedup vs baseline: 1.0026x; 1.0026x over previous
#include <cuda_runtime.h>

#define BB 16
#define HH 1024
#define WW 1024
#define R 4
#define KS 9
#define TX 64
#define TY 32
#define NT 256
#define IW (TX + 2*R)   // 72
#define IH (TY + 2*R)   // 40
#define ROWS_PER_THREAD (TY / (NT / TX))   // 8

__device__ double g_loss_acc;

__global__ void zero_acc_kernel() { g_loss_acc = 0.0; }

__global__ void finalize_kernel(float* out) {
    out[0] = (float)(g_loss_acc / (double)((long long)BB * HH * WW));
}

__global__ __launch_bounds__(NT) void snake_fused_kernel(
    const float* __restrict__ pred,
    const float* __restrict__ snake,
    const float* __restrict__ fltr,
    float* __restrict__ out)
{
    __shared__ float s_in[IH][IW];       // 40 x 72 input tile (with halo)
    __shared__ float s_hg[IH][TX];       // horizontal conv with g
    __shared__ float s_hd[IH][TX];       // horizontal conv with dg
    __shared__ float s_g[KS], s_dg[KS];
    __shared__ float s_red[NT / 32];

    const int tid = threadIdx.x;
    const int bx = blockIdx.x;   // W / TX = 16
    const int by = blockIdx.y;   // H / TY = 32
    const int b  = blockIdx.z;   // B = 16

    // --- recover separable taps from fltr (f_dy = outer(dg, g), sum(g)=1) ---
    if (tid < KS) {
        float s = 0.f;
        #pragma unroll
        for (int j = 0; j < KS; ++j) s += fltr[tid * KS + j];  // row-sum of f_dy -> dg[i]
        s_dg[tid] = s;
    }
    __syncthreads();
    if (tid < KS) {
        s_g[tid] = fltr[tid] / s_dg[0];  // f_dy[0][j] / dg[0] = g[j]
    }

    // --- load input tile with halo (zero-padded SAME) ---
    const int x0 = bx * TX - R;
    const int y0 = by * TY - R;
    const size_t plane = (size_t)HH * WW;
    const float* pb = pred + (size_t)b * plane;
    for (int i = tid; i < IW * IH; i += NT) {
        int rx = i % IW, ry = i / IW;
        int gx = x0 + rx, gy = y0 + ry;
        float v = 0.f;
        if (gx >= 0 && gx < WW && gy >= 0 && gy < HH) v = pb[(size_t)gy * WW + gx];
        s_in[ry][rx] = v;
    }
    __syncthreads();

    float rg[KS], rdg[KS];
    #pragma unroll
    for (int j = 0; j < KS; ++j) { rg[j] = s_g[j]; rdg[j] = s_dg[j]; }

    const int tx  = tid % TX;
    const int tyb = tid / TX;   // 0..3
    float* out_gimg  = out + 1;
    float* out_gimgW = out + 1 + (size_t)BB * 2 * plane;
    const float* sb = snake + (size_t)b * plane;

    // ================= Phase A: raw conv + loss =================
    for (int i = tid; i < IH * TX; i += NT) {
        int cx = i % TX, ry = i / TX;
        float sg = 0.f, sd = 0.f;
        #pragma unroll
        for (int j = 0; j < KS; ++j) {
            float v = s_in[ry][cx + j];
            sg = fmaf(rg[j],  v, sg);
            sd = fmaf(rdg[j], v, sd);
        }
        s_hg[ry][cx] = sg;
        s_hd[ry][cx] = sd;
    }
    __syncthreads();

    float lacc = 0.f;
    #pragma unroll
    for (int k = 0; k < ROWS_PER_THREAD; ++k) {
        int ty = tyb + k * (NT / TX);
        float ady = 0.f, adx = 0.f;
        #pragma unroll
        for (int j = 0; j < KS; ++j) {
            ady = fmaf(rdg[j], s_hg[ty + j][tx], ady);  // dy channel: dg over y, g over x
            adx = fmaf(rg[j],  s_hd[ty + j][tx], adx);  // dx channel: g over y, dg over x
        }
        int gy = by * TY + ty;
        int gx = bx * TX + tx;
        size_t pix = (size_t)gy * WW + gx;
        out_gimg[((size_t)b * 2 + 0) * plane + pix] = 10.0f * ady;
        out_gimg[((size_t)b * 2 + 1) * plane + pix] = 10.0f * adx;

        // loss: sd = s>0 ? DMAX : 2*s ; weight = 1 + 1.5*(s<0)
        float p = s_in[ty + R][tx + R];
        float s = sb[pix];
        float sdv = (s > 0.f) ? 15.0f : 2.0f * s;
        float w   = (s < 0.f) ? 2.5f : 1.0f;
        float d = p - sdv;
        lacc = fmaf(d * d, w, lacc);
    }
    __syncthreads();   // done reading s_hg/s_hd/s_in(loss) before overwrite

    // ================= Phase B: abs(pred) conv =================
    for (int i = tid; i < IH * TX; i += NT) {
        int cx = i % TX, ry = i / TX;
        float sg = 0.f, sd = 0.f;
        #pragma unroll
        for (int j = 0; j < KS; ++j) {
            float v = fabsf(s_in[ry][cx + j]);
            sg = fmaf(rg[j],  v, sg);
            sd = fmaf(rdg[j], v, sd);
        }
        s_hg[ry][cx] = sg;
        s_hd[ry][cx] = sd;
    }
    __syncthreads();

    #pragma unroll
    for (int k = 0; k < ROWS_PER_THREAD; ++k) {
        int ty = tyb + k * (NT / TX);
        float ady = 0.f, adx = 0.f;
        #pragma unroll
        for (int j = 0; j < KS; ++j) {
            ady = fmaf(rdg[j], s_hg[ty + j][tx], ady);
            adx = fmaf(rg[j],  s_hd[ty + j][tx], adx);
        }
        int gy = by * TY + ty;
        int gx = bx * TX + tx;
        size_t pix = (size_t)gy * WW + gx;
        out_gimgW[((size_t)b * 2 + 0) * plane + pix] = 10.0f * ady;
        out_gimgW[((size_t)b * 2 + 1) * plane + pix] = 10.0f * adx;
    }

    // ================= loss block reduce =================
    #pragma unroll
    for (int off = 16; off; off >>= 1)
        lacc += __shfl_down_sync(0xffffffffu, lacc, off);
    if ((tid & 31) == 0) s_red[tid >> 5] = lacc;
    __syncthreads();
    if (tid < NT / 32) {
        float v = s_red[tid];
        #pragma unroll
        for (int off = (NT / 64); off; off >>= 1)
            v += __shfl_down_sync(0xffu, v, off);
        if (tid == 0) atomicAdd(&g_loss_acc, (double)v);
    }
}

extern "C" void kernel_launch(void* const* d_in, const int* in_sizes, int n_in,
                              void* d_out, int out_size) {
    const float* pred  = (const float*)d_in[0];
    const float* snake = (const float*)d_in[1];
    const float* fltr  = (const float*)d_in[2];
    float* out = (float*)d_out;

    zero_acc_kernel<<<1, 1>>>();
    dim3 grid(WW / TX, HH / TY, BB);
    snake_fused_kernel<<<grid, NT>>>(pred, snake, fltr, out);
    finalize_kernel<<<1, 1>>>(out);
}